// round 13
// baseline (speedup 1.0000x reference)
#include <cuda_runtime.h>
#include <cuda_fp16.h>
#include <math.h>
#include <stdint.h>

#define NODES 100000
#define GRAPHS 100
#define NPG 1000
#define CH 128
#define OUTD 64
#define POSD 16
#define TM 64
#define NBLK ((NODES + TM - 1) / TM)   // 1563
#define PGRID 521                      // 521*3 == 1563; single wave (<= 4*148)
#define DSMEM 49152                    // At/stage 16K | Wt 32K

// ---- device-global scratch (statically zero-initialized at load) ----
__device__ __half g_y0[(size_t)NODES * CH];
__device__ __half g_y1[(size_t)NODES * CH];
__device__ float g_sum[2][CH];
__device__ float g_sq[2][CH];
__device__ float g_pool[GRAPHS * CH];
__device__ volatile unsigned g_bar[2];

__device__ __forceinline__ uint32_t smem_u32(const void* p) {
    uint32_t a;
    asm("{ .reg .u64 t; cvta.to.shared.u64 t, %1; cvt.u32.u64 %0, t; }" : "=r"(a) : "l"(p));
    return a;
}
__device__ __forceinline__ uint32_t swz(uint32_t row, uint32_t chunk) {
    return row * 256u + ((chunk ^ (row & 7u)) << 4);
}
__device__ __forceinline__ void ldsm4(uint32_t& r0, uint32_t& r1, uint32_t& r2, uint32_t& r3,
                                      uint32_t addr) {
    asm volatile("ldmatrix.sync.aligned.m8n8.x4.shared.b16 {%0,%1,%2,%3}, [%4];"
                 : "=r"(r0), "=r"(r1), "=r"(r2), "=r"(r3) : "r"(addr));
}
__device__ __forceinline__ void mma_f16(float* c, uint32_t a0, uint32_t a1, uint32_t a2,
                                        uint32_t a3, uint32_t b0, uint32_t b1) {
    asm volatile(
        "mma.sync.aligned.m16n8k16.row.col.f32.f16.f16.f32 "
        "{%0,%1,%2,%3}, {%4,%5,%6,%7}, {%8,%9}, {%0,%1,%2,%3};"
        : "+f"(c[0]), "+f"(c[1]), "+f"(c[2]), "+f"(c[3])
        : "r"(a0), "r"(a1), "r"(a2), "r"(a3), "r"(b0), "r"(b1));
}
__device__ __forceinline__ uint32_t h2u(__half2 h) {
    uint32_t u;
    memcpy(&u, &h, 4);
    return u;
}
__device__ __forceinline__ float elu_fast(float x) {
    return (x > 0.f) ? x : (__expf(x) - 1.f);
}
__device__ __forceinline__ void grid_sync(int ph) {
    __syncthreads();
    if (threadIdx.x == 0) {
        __threadfence();
        atomicAdd((unsigned*)&g_bar[ph], 1u);
        while (g_bar[ph] < PGRID) { }
        __threadfence();
    }
    __syncthreads();
}

// build swizzled fp16 W tile in smem from raw fp32 weights [CH][wstride]
__device__ __forceinline__ void build_W(char* Wt, const float* __restrict__ W, int wstride,
                                        int tid) {
#pragma unroll
    for (int i = 0; i < 8; i++) {
        int u = tid + 256 * i;            // 0..2047
        int c = u >> 4;
        int chunk = u & 15;
        const float4* src = (const float4*)(W + (size_t)c * wstride + chunk * 8);
        float4 p0 = src[0], p1 = src[1];
        uint4 packed;
        packed.x = h2u(__floats2half2_rn(p0.x, p0.y));
        packed.y = h2u(__floats2half2_rn(p0.z, p0.w));
        packed.z = h2u(__floats2half2_rn(p1.x, p1.y));
        packed.w = h2u(__floats2half2_rn(p1.z, p1.w));
        *(uint4*)(Wt + swz((uint32_t)c, (uint32_t)chunk)) = packed;
    }
}

// ---- fully fused persistent kernel: prologue | layer0 | sync | layer1 | sync | pool ----
__global__ __launch_bounds__(256, 4) void k_fused(const float* __restrict__ xin,
                                                  const float* __restrict__ peW,
                                                  const float* __restrict__ peB,
                                                  const float* __restrict__ W0,
                                                  const float* __restrict__ b0,
                                                  const float* __restrict__ g0,
                                                  const float* __restrict__ bb0,
                                                  const float* __restrict__ W1,
                                                  const float* __restrict__ b1,
                                                  const float* __restrict__ g1,
                                                  const float* __restrict__ bb1) {
    extern __shared__ char sm[];
    char* At = sm;
    char* Wt = sm + 16384;
    uint32_t* stg32 = (uint32_t*)sm;

    __shared__ float s_B[CH], s_M0x[CH], s_M0y[CH], s_sc[CH], s_sh[CH];

    int tid = threadIdx.x;
    int wid = tid >> 5;
    int lane = tid & 31;

    int wr = wid >> 2;
    int wc = wid & 3;
    uint32_t la7 = lane & 7;
    uint32_t aSel = (uint32_t)(lane >> 4);
    uint32_t r0base = (uint32_t)(32 * wr + (lane & 15));
    uint32_t bRow = (uint32_t)(32 * wc + (lane & 7) + ((lane >> 4) << 3)) * 256u;
    uint32_t bSel = (uint32_t)((lane >> 3) & 1);
    uint32_t baseA = smem_u32(At), baseW = smem_u32(Wt);
    int tr = lane >> 2;
    int tcq = lane & 3;
    int wcp = tid & 63;
    int wcc = wcp * 2;
    int grp = tid >> 6;

    // ---- prologue: W0 tile + folded positional constants ----
    build_W(Wt, W0, 144, tid);
    if (tid < CH) {
        int c = tid;
        float m0 = 0.f, m1 = 0.f, be = 0.f;
#pragma unroll
        for (int k = 0; k < POSD; k++) {
            float w = W0[c * 144 + 128 + k];
            m0 += peW[2 * k] * w;
            m1 += peW[2 * k + 1] * w;
            be += peB[k] * w;
        }
        s_M0x[c] = m0;
        s_M0y[c] = m1;
        s_B[c] = be + b0[c];
    }
    float as0 = 0.f, aq0 = 0.f, as1 = 0.f, aq1 = 0.f;
    __syncthreads();

    // =============== PHASE A: layer 0 ===============
#pragma unroll 1
    for (int tile = blockIdx.x; tile < NBLK; tile += PGRID) {
        int nb = tile * TM;
#pragma unroll
        for (int i = 0; i < 4; i++) {
            int u = tid + 256 * i;
            int row = u >> 4;
            int chunk = u & 15;
            int gn = nb + row;
            uint4 packed = make_uint4(0, 0, 0, 0);
            if (gn < NODES) {
                const float4* src4 = (const float4*)xin;
                float4 p0 = src4[(size_t)gn * 32 + chunk * 2];
                float4 p1 = src4[(size_t)gn * 32 + chunk * 2 + 1];
                packed.x = h2u(__floats2half2_rn(p0.x, p0.y));
                packed.y = h2u(__floats2half2_rn(p0.z, p0.w));
                packed.z = h2u(__floats2half2_rn(p1.x, p1.y));
                packed.w = h2u(__floats2half2_rn(p1.z, p1.w));
            }
            *(uint4*)(At + swz((uint32_t)row, (uint32_t)chunk)) = packed;
        }
        __syncthreads();

        float C[2][4][4];
#pragma unroll
        for (int mt = 0; mt < 2; mt++)
#pragma unroll
            for (int n = 0; n < 4; n++)
#pragma unroll
                for (int j = 0; j < 4; j++) C[mt][n][j] = 0.f;
#pragma unroll
        for (int ks = 0; ks < 8; ks++) {
            uint32_t asw = (((2 * ks + aSel) ^ la7) << 4);
            uint32_t ah[2][4];
#pragma unroll
            for (int mt = 0; mt < 2; mt++) {
                uint32_t ar = (r0base + 16 * mt) * 256u + asw;
                ldsm4(ah[mt][0], ah[mt][1], ah[mt][2], ah[mt][3], baseA + ar);
            }
            uint32_t bsw = (((2 * ks + bSel) ^ la7) << 4);
#pragma unroll
            for (int np = 0; np < 2; np++) {
                uint32_t boff = bRow + np * 4096 + bsw;
                uint32_t w0, w1, w2, w3;
                ldsm4(w0, w1, w2, w3, baseW + boff);
#pragma unroll
                for (int mt = 0; mt < 2; mt++) {
                    mma_f16(C[mt][2 * np],     ah[mt][0], ah[mt][1], ah[mt][2], ah[mt][3], w0, w1);
                    mma_f16(C[mt][2 * np + 1], ah[mt][0], ah[mt][1], ah[mt][2], ah[mt][3], w2, w3);
                }
            }
        }
        __syncthreads();

#pragma unroll
        for (int mt = 0; mt < 2; mt++) {
            int ra = 32 * wr + 16 * mt + tr;
            int rb = ra + 8;
            int na = nb + ra, nbo = nb + rb;
            int la = na - (na / NPG) * NPG;
            int lb = nbo - (nbo / NPG) * NPG;
            float pxa = (float)(la >> 5) * (1.f / 31.f);
            float pya = (float)(la & 31) * (1.f / 31.f);
            float pxb = (float)(lb >> 5) * (1.f / 31.f);
            float pyb = (float)(lb & 31) * (1.f / 31.f);
#pragma unroll
            for (int nt = 0; nt < 4; nt++) {
                int c = 32 * wc + 8 * nt + 2 * tcq;
                float v0 = C[mt][nt][0] + s_B[c]     + pxa * s_M0x[c]     + pya * s_M0y[c];
                float v1 = C[mt][nt][1] + s_B[c + 1] + pxa * s_M0x[c + 1] + pya * s_M0y[c + 1];
                float v2 = C[mt][nt][2] + s_B[c]     + pxb * s_M0x[c]     + pyb * s_M0y[c];
                float v3 = C[mt][nt][3] + s_B[c + 1] + pxb * s_M0x[c + 1] + pyb * s_M0y[c + 1];
                uint32_t cp = (uint32_t)(16 * wc + 4 * nt + tcq);
                stg32[(uint32_t)ra * 64u + (cp ^ (((uint32_t)ra & 7u) << 2))] =
                    h2u(__floats2half2_rn(v0, v1));
                stg32[(uint32_t)rb * 64u + (cp ^ (((uint32_t)rb & 7u) << 2))] =
                    h2u(__floats2half2_rn(v2, v3));
            }
        }
        __syncthreads();

#pragma unroll 4
        for (int r = grp * 16; r < grp * 16 + 16; r++) {
            int node = nb + r;
            if (node < NODES) {
                uint32_t hv = stg32[(uint32_t)r * 64u +
                                    ((uint32_t)wcp ^ (((uint32_t)r & 7u) << 2))];
                *(uint32_t*)&g_y0[(size_t)node * CH + wcc] = hv;
                __half2 h;
                memcpy(&h, &hv, 4);
                float2 f = __half22float2(h);
                as0 += f.x; aq0 += f.x * f.x;
                as1 += f.y; aq1 += f.y * f.y;
            }
        }
        __syncthreads();
    }
    ((float4*)sm)[tid] = make_float4(as0, aq0, as1, aq1);
    __syncthreads();
    if (tid < 64) {
        float4 a = ((float4*)sm)[tid], b = ((float4*)sm)[tid + 64];
        float4 cc = ((float4*)sm)[tid + 128], d = ((float4*)sm)[tid + 192];
        int c = tid * 2;
        atomicAdd(&g_sum[0][c],     a.x + b.x + cc.x + d.x);
        atomicAdd(&g_sq[0][c],      a.y + b.y + cc.y + d.y);
        atomicAdd(&g_sum[0][c + 1], a.z + b.z + cc.z + d.z);
        atomicAdd(&g_sq[0][c + 1],  a.w + b.w + cc.w + d.w);
    }
    grid_sync(0);

    // ---- swap to W1 + BN0 scale/shift + bias1 ----
    build_W(Wt, W1, CH, tid);
    if (tid < CH) {
        s_B[tid] = b1[tid];
        float mu = g_sum[0][tid] * (1.f / NODES);
        float var = g_sq[0][tid] * (1.f / NODES) - mu * mu;
        float sc = g0[tid] * rsqrtf(var + 1e-5f);
        s_sc[tid] = sc;
        s_sh[tid] = bb0[tid] - mu * sc;
    }
    as0 = 0.f; aq0 = 0.f; as1 = 0.f; aq1 = 0.f;
    __syncthreads();

    // =============== PHASE B: layer 1 ===============
#pragma unroll 1
    for (int tile = blockIdx.x; tile < NBLK; tile += PGRID) {
        int nb = tile * TM;
#pragma unroll
        for (int i = 0; i < 4; i++) {
            int u = tid + 256 * i;
            int row = u >> 4;
            int chunk = u & 15;
            int gn = nb + row;
            uint4 packed = make_uint4(0, 0, 0, 0);
            if (gn < NODES) {
                uint4 raw = *(const uint4*)&g_y0[(size_t)gn * CH + chunk * 8];
                uint32_t rr[4] = {raw.x, raw.y, raw.z, raw.w};
                uint32_t oo[4];
#pragma unroll
                for (int j = 0; j < 4; j++) {
                    __half2 h;
                    memcpy(&h, &rr[j], 4);
                    float2 f = __half22float2(h);
                    int c = chunk * 8 + 2 * j;
                    float a0 = elu_fast(f.x * s_sc[c] + s_sh[c]);
                    float a1 = elu_fast(f.y * s_sc[c + 1] + s_sh[c + 1]);
                    oo[j] = h2u(__floats2half2_rn(a0, a1));
                }
                packed = make_uint4(oo[0], oo[1], oo[2], oo[3]);
            }
            *(uint4*)(At + swz((uint32_t)row, (uint32_t)chunk)) = packed;
        }
        __syncthreads();

        float C[2][4][4];
#pragma unroll
        for (int mt = 0; mt < 2; mt++)
#pragma unroll
            for (int n = 0; n < 4; n++)
#pragma unroll
                for (int j = 0; j < 4; j++) C[mt][n][j] = 0.f;
#pragma unroll
        for (int ks = 0; ks < 8; ks++) {
            uint32_t asw = (((2 * ks + aSel) ^ la7) << 4);
            uint32_t ah[2][4];
#pragma unroll
            for (int mt = 0; mt < 2; mt++) {
                uint32_t ar = (r0base + 16 * mt) * 256u + asw;
                ldsm4(ah[mt][0], ah[mt][1], ah[mt][2], ah[mt][3], baseA + ar);
            }
            uint32_t bsw = (((2 * ks + bSel) ^ la7) << 4);
#pragma unroll
            for (int np = 0; np < 2; np++) {
                uint32_t boff = bRow + np * 4096 + bsw;
                uint32_t w0, w1, w2, w3;
                ldsm4(w0, w1, w2, w3, baseW + boff);
#pragma unroll
                for (int mt = 0; mt < 2; mt++) {
                    mma_f16(C[mt][2 * np],     ah[mt][0], ah[mt][1], ah[mt][2], ah[mt][3], w0, w1);
                    mma_f16(C[mt][2 * np + 1], ah[mt][0], ah[mt][1], ah[mt][2], ah[mt][3], w2, w3);
                }
            }
        }
        __syncthreads();

#pragma unroll
        for (int mt = 0; mt < 2; mt++) {
            int ra = 32 * wr + 16 * mt + tr;
            int rb = ra + 8;
#pragma unroll
            for (int nt = 0; nt < 4; nt++) {
                int c = 32 * wc + 8 * nt + 2 * tcq;
                float v0 = C[mt][nt][0] + s_B[c];
                float v1 = C[mt][nt][1] + s_B[c + 1];
                float v2 = C[mt][nt][2] + s_B[c];
                float v3 = C[mt][nt][3] + s_B[c + 1];
                uint32_t cp = (uint32_t)(16 * wc + 4 * nt + tcq);
                stg32[(uint32_t)ra * 64u + (cp ^ (((uint32_t)ra & 7u) << 2))] =
                    h2u(__floats2half2_rn(v0, v1));
                stg32[(uint32_t)rb * 64u + (cp ^ (((uint32_t)rb & 7u) << 2))] =
                    h2u(__floats2half2_rn(v2, v3));
            }
        }
        __syncthreads();

#pragma unroll 4
        for (int r = grp * 16; r < grp * 16 + 16; r++) {
            int node = nb + r;
            if (node < NODES) {
                uint32_t hv = stg32[(uint32_t)r * 64u +
                                    ((uint32_t)wcp ^ (((uint32_t)r & 7u) << 2))];
                *(uint32_t*)&g_y1[(size_t)node * CH + wcc] = hv;
                __half2 h;
                memcpy(&h, &hv, 4);
                float2 f = __half22float2(h);
                as0 += f.x; aq0 += f.x * f.x;
                as1 += f.y; aq1 += f.y * f.y;
            }
        }
        __syncthreads();
    }
    ((float4*)sm)[tid] = make_float4(as0, aq0, as1, aq1);
    __syncthreads();
    if (tid < 64) {
        float4 a = ((float4*)sm)[tid], b = ((float4*)sm)[tid + 64];
        float4 cc = ((float4*)sm)[tid + 128], d = ((float4*)sm)[tid + 192];
        int c = tid * 2;
        atomicAdd(&g_sum[1][c],     a.x + b.x + cc.x + d.x);
        atomicAdd(&g_sq[1][c],      a.y + b.y + cc.y + d.y);
        atomicAdd(&g_sum[1][c + 1], a.z + b.z + cc.z + d.z);
        atomicAdd(&g_sq[1][c + 1],  a.w + b.w + cc.w + d.w);
    }
    grid_sync(1);

    // =============== PHASE C: pool over own tiles ===============
    {
        float mu0 = g_sum[1][wcc] * (1.f / NODES);
        float va0 = g_sq[1][wcc] * (1.f / NODES) - mu0 * mu0;
        float sc0 = g1[wcc] * rsqrtf(va0 + 1e-5f);
        float sh0 = bb1[wcc] - mu0 * sc0;
        float mu1 = g_sum[1][wcc + 1] * (1.f / NODES);
        float va1 = g_sq[1][wcc + 1] * (1.f / NODES) - mu1 * mu1;
        float sc1 = g1[wcc + 1] * rsqrtf(va1 + 1e-5f);
        float sh1 = bb1[wcc + 1] - mu1 * sc1;

#pragma unroll 1
        for (int tile = blockIdx.x; tile < NBLK; tile += PGRID) {
            int nb = tile * TM;
            int gcur = -1;
            float p0 = 0.f, p1 = 0.f;
#pragma unroll 4
            for (int r = grp * 16; r < grp * 16 + 16; r++) {
                int node = nb + r;
                if (node >= NODES) break;
                int gg = node / NPG;
                if (gg != gcur) {
                    if (gcur >= 0) {
                        atomicAdd(&g_pool[gcur * CH + wcc], p0);
                        atomicAdd(&g_pool[gcur * CH + wcc + 1], p1);
                    }
                    gcur = gg; p0 = 0.f; p1 = 0.f;
                }
                uint32_t hv = *(const uint32_t*)&g_y1[(size_t)node * CH + wcc];
                __half2 h;
                memcpy(&h, &hv, 4);
                float2 f = __half22float2(h);
                p0 += elu_fast(f.x * sc0 + sh0);
                p1 += elu_fast(f.y * sc1 + sh1);
            }
            if (gcur >= 0) {
                atomicAdd(&g_pool[gcur * CH + wcc], p0);
                atomicAdd(&g_pool[gcur * CH + wcc + 1], p1);
            }
        }
    }
}

// ---- FC + reset of accumulators/barriers for the next graph replay ----
__global__ void k_fc(const float* __restrict__ fcW, const float* __restrict__ fcb,
                     float* __restrict__ out) {
    int g = blockIdx.x;
    int o = threadIdx.x;
    float s = 0.f;
#pragma unroll 8
    for (int c = 0; c < CH; c++) s += g_pool[g * CH + c] * fcW[o * CH + c];
    out[g * OUTD + o] = s * (1.f / NPG) + fcb[o];
    __syncthreads();
    // reset this graph's pool row
    g_pool[g * CH + o] = 0.f;
    g_pool[g * CH + 64 + o] = 0.f;
    if (g == 0) {
        g_sum[0][o] = 0.f; g_sum[0][64 + o] = 0.f;
        g_sum[1][o] = 0.f; g_sum[1][64 + o] = 0.f;
        g_sq[0][o] = 0.f;  g_sq[0][64 + o] = 0.f;
        g_sq[1][o] = 0.f;  g_sq[1][64 + o] = 0.f;
        if (o < 2) g_bar[o] = 0u;
    }
}

extern "C" void kernel_launch(void* const* d_in, const int* in_sizes, int n_in,
                              void* d_out, int out_size) {
    const float* x   = (const float*)d_in[0];
    const float* peW = (const float*)d_in[3];
    const float* peB = (const float*)d_in[4];
    const float* W0  = (const float*)d_in[5];
    const float* b0  = (const float*)d_in[8];
    const float* g0  = (const float*)d_in[9];
    const float* bb0 = (const float*)d_in[10];
    const float* W1  = (const float*)d_in[11];
    const float* b1  = (const float*)d_in[14];
    const float* g1  = (const float*)d_in[15];
    const float* bb1 = (const float*)d_in[16];
    const float* fcW = (const float*)d_in[17];
    const float* fcb = (const float*)d_in[18];
    float* out = (float*)d_out;

    static bool once = false;
    if (!once) {
        cudaFuncSetAttribute(k_fused, cudaFuncAttributeMaxDynamicSharedMemorySize, DSMEM);
        once = true;
    }

    k_fused<<<PGRID, 256, DSMEM>>>(x, peW, peB, W0, b0, g0, bb0, W1, b1, g1, bb1);
    k_fc<<<GRAPHS, OUTD>>>(fcW, fcb, out);
}

// round 14
// speedup vs baseline: 1.1337x; 1.1337x over previous
#include <cuda_runtime.h>
#include <cuda_fp16.h>
#include <math.h>
#include <stdint.h>

#define NODES 100000
#define GRAPHS 100
#define NPG 1000
#define CH 128
#define OUTD 64
#define POSD 16
#define TM 64
#define NBLK ((NODES + TM - 1) / TM)   // 1563
#define PGRID 521                      // 521*3 == 1563; single wave (<= 4*148)
#define DSMEM 49152                    // At/stage 16K | Wt 32K

// ---- device-global scratch ----
__device__ __half g_y0[(size_t)NODES * CH];
__device__ __half g_y1[(size_t)NODES * CH];
__device__ unsigned char g_Wimg[2][32768];
__device__ float g_M0[2 * CH];
__device__ float g_beff0[CH];
__device__ float g_sum[2][CH];
__device__ float g_sq[2][CH];
__device__ float g_pool[GRAPHS * CH];
__device__ volatile unsigned g_bar[2];

__device__ __forceinline__ uint32_t smem_u32(const void* p) {
    uint32_t a;
    asm("{ .reg .u64 t; cvta.to.shared.u64 t, %1; cvt.u32.u64 %0, t; }" : "=r"(a) : "l"(p));
    return a;
}
__device__ __forceinline__ uint32_t swz(uint32_t row, uint32_t chunk) {
    return row * 256u + ((chunk ^ (row & 7u)) << 4);
}
__device__ __forceinline__ void ldsm4(uint32_t& r0, uint32_t& r1, uint32_t& r2, uint32_t& r3,
                                      uint32_t addr) {
    asm volatile("ldmatrix.sync.aligned.m8n8.x4.shared.b16 {%0,%1,%2,%3}, [%4];"
                 : "=r"(r0), "=r"(r1), "=r"(r2), "=r"(r3) : "r"(addr));
}
__device__ __forceinline__ void mma_f16(float* c, uint32_t a0, uint32_t a1, uint32_t a2,
                                        uint32_t a3, uint32_t b0, uint32_t b1) {
    asm volatile(
        "mma.sync.aligned.m16n8k16.row.col.f32.f16.f16.f32 "
        "{%0,%1,%2,%3}, {%4,%5,%6,%7}, {%8,%9}, {%0,%1,%2,%3};"
        : "+f"(c[0]), "+f"(c[1]), "+f"(c[2]), "+f"(c[3])
        : "r"(a0), "r"(a1), "r"(a2), "r"(a3), "r"(b0), "r"(b1));
}
__device__ __forceinline__ uint32_t h2u(__half2 h) {
    uint32_t u;
    memcpy(&u, &h, 4);
    return u;
}
__device__ __forceinline__ float elu_fast(float x) {
    return (x > 0.f) ? x : (__expf(x) - 1.f);
}
__device__ __forceinline__ void grid_sync(int ph) {
    __syncthreads();
    if (threadIdx.x == 0) {
        __threadfence();
        atomicAdd((unsigned*)&g_bar[ph], 1u);
        while (g_bar[ph] < PGRID) { }
        __threadfence();
    }
    __syncthreads();
}

__global__ void k_prep(const float* __restrict__ peW, const float* __restrict__ peB,
                       const float* __restrict__ W0, const float* __restrict__ b0,
                       const float* __restrict__ W1) {
    int t = blockIdx.x * blockDim.x + threadIdx.x;
    int stride = gridDim.x * blockDim.x;
    if (t < 2) g_bar[t] = 0u;
    for (int i = t; i < GRAPHS * CH; i += stride) g_pool[i] = 0.f;
    for (int i = t; i < CH; i += stride) {
        g_sum[0][i] = 0.f; g_sum[1][i] = 0.f;
        g_sq[0][i] = 0.f;  g_sq[1][i] = 0.f;
    }
    for (int i = t; i < 2 * CH * CH; i += stride) {
        int layer = i >> 14, e = i & 16383, c = e >> 7, k = e & 127;
        float w = layer ? W1[c * CH + k] : W0[c * 144 + k];
        uint32_t off = swz((uint32_t)c, (uint32_t)(k >> 3)) + (k & 7) * 2;
        *(__half*)(g_Wimg[layer] + off) = __float2half_rn(w);
    }
    if (blockIdx.x == 0 && threadIdx.x < CH) {
        int c = threadIdx.x;
        float m0 = 0.f, m1 = 0.f, be = 0.f;
        for (int k = 0; k < POSD; k++) {
            float w = W0[c * 144 + 128 + k];
            m0 += peW[2 * k] * w;
            m1 += peW[2 * k + 1] * w;
            be += peB[k] * w;
        }
        g_M0[c] = m0; g_M0[CH + c] = m1;
        g_beff0[c] = be + b0[c];
    }
}

// ---- fully fused persistent kernel: layer0 | sync | layer1 | sync | pool ----
__global__ __launch_bounds__(256, 4) void k_fused(const float* __restrict__ xin,
                                                  const float* __restrict__ bias1,
                                                  const float* __restrict__ g0,
                                                  const float* __restrict__ bb0,
                                                  const float* __restrict__ g1,
                                                  const float* __restrict__ bb1) {
    extern __shared__ char sm[];
    char* At = sm;
    char* Wt = sm + 16384;
    uint32_t* stg32 = (uint32_t*)sm;

    __shared__ float s_B[CH], s_M0x[CH], s_M0y[CH], s_sc[CH], s_sh[CH];

    int tid = threadIdx.x;
    int wid = tid >> 5;
    int lane = tid & 31;

    int wr = wid >> 2;
    int wc = wid & 3;
    uint32_t la7 = lane & 7;
    uint32_t aSel = (uint32_t)(lane >> 4);
    uint32_t r0base = (uint32_t)(32 * wr + (lane & 15));
    uint32_t bRow = (uint32_t)(32 * wc + (lane & 7) + ((lane >> 4) << 3)) * 256u;
    uint32_t bSel = (uint32_t)((lane >> 3) & 1);
    uint32_t baseA = smem_u32(At), baseW = smem_u32(Wt);
    int tr = lane >> 2;
    int tcq = lane & 3;
    int wcp = tid & 63;
    int wcc = wcp * 2;
    int grp = tid >> 6;

    // ---- W0 image + constants ----
    {
        const char* wsrc = (const char*)g_Wimg[0];
        uint32_t wdst = smem_u32(Wt);
#pragma unroll
        for (int i = 0; i < 8; i++) {
            uint32_t off = (uint32_t)(tid + 256 * i) * 16u;
            asm volatile("cp.async.cg.shared.global [%0], [%1], 16;"
                         :: "r"(wdst + off), "l"(wsrc + off));
        }
        asm volatile("cp.async.commit_group;");
    }
    if (tid < CH) {
        s_B[tid] = g_beff0[tid];
        s_M0x[tid] = g_M0[tid];
        s_M0y[tid] = g_M0[CH + tid];
    }
    float as0 = 0.f, aq0 = 0.f, as1 = 0.f, aq1 = 0.f;
    asm volatile("cp.async.wait_group 0;");
    __syncthreads();

    // =============== PHASE A: layer 0 ===============
#pragma unroll 1
    for (int tile = blockIdx.x; tile < NBLK; tile += PGRID) {
        int nb = tile * TM;
#pragma unroll
        for (int i = 0; i < 4; i++) {
            int u = tid + 256 * i;
            int row = u >> 4;
            int chunk = u & 15;
            int gn = nb + row;
            uint4 packed = make_uint4(0, 0, 0, 0);
            if (gn < NODES) {
                const float4* src4 = (const float4*)xin;
                float4 p0 = src4[(size_t)gn * 32 + chunk * 2];
                float4 p1 = src4[(size_t)gn * 32 + chunk * 2 + 1];
                packed.x = h2u(__floats2half2_rn(p0.x, p0.y));
                packed.y = h2u(__floats2half2_rn(p0.z, p0.w));
                packed.z = h2u(__floats2half2_rn(p1.x, p1.y));
                packed.w = h2u(__floats2half2_rn(p1.z, p1.w));
            }
            *(uint4*)(At + swz((uint32_t)row, (uint32_t)chunk)) = packed;
        }
        __syncthreads();

        float C[2][4][4];
#pragma unroll
        for (int mt = 0; mt < 2; mt++)
#pragma unroll
            for (int n = 0; n < 4; n++)
#pragma unroll
                for (int j = 0; j < 4; j++) C[mt][n][j] = 0.f;
#pragma unroll
        for (int ks = 0; ks < 8; ks++) {
            uint32_t asw = (((2 * ks + aSel) ^ la7) << 4);
            uint32_t ah[2][4];
#pragma unroll
            for (int mt = 0; mt < 2; mt++) {
                uint32_t ar = (r0base + 16 * mt) * 256u + asw;
                ldsm4(ah[mt][0], ah[mt][1], ah[mt][2], ah[mt][3], baseA + ar);
            }
            uint32_t bsw = (((2 * ks + bSel) ^ la7) << 4);
#pragma unroll
            for (int np = 0; np < 2; np++) {
                uint32_t boff = bRow + np * 4096 + bsw;
                uint32_t w0, w1, w2, w3;
                ldsm4(w0, w1, w2, w3, baseW + boff);
#pragma unroll
                for (int mt = 0; mt < 2; mt++) {
                    mma_f16(C[mt][2 * np],     ah[mt][0], ah[mt][1], ah[mt][2], ah[mt][3], w0, w1);
                    mma_f16(C[mt][2 * np + 1], ah[mt][0], ah[mt][1], ah[mt][2], ah[mt][3], w2, w3);
                }
            }
        }
        __syncthreads();

#pragma unroll
        for (int mt = 0; mt < 2; mt++) {
            int ra = 32 * wr + 16 * mt + tr;
            int rb = ra + 8;
            int na = nb + ra, nbo = nb + rb;
            int la = na - (na / NPG) * NPG;
            int lb = nbo - (nbo / NPG) * NPG;
            float pxa = (float)(la >> 5) * (1.f / 31.f);
            float pya = (float)(la & 31) * (1.f / 31.f);
            float pxb = (float)(lb >> 5) * (1.f / 31.f);
            float pyb = (float)(lb & 31) * (1.f / 31.f);
#pragma unroll
            for (int nt = 0; nt < 4; nt++) {
                int c = 32 * wc + 8 * nt + 2 * tcq;
                float v0 = C[mt][nt][0] + s_B[c]     + pxa * s_M0x[c]     + pya * s_M0y[c];
                float v1 = C[mt][nt][1] + s_B[c + 1] + pxa * s_M0x[c + 1] + pya * s_M0y[c + 1];
                float v2 = C[mt][nt][2] + s_B[c]     + pxb * s_M0x[c]     + pyb * s_M0y[c];
                float v3 = C[mt][nt][3] + s_B[c + 1] + pxb * s_M0x[c + 1] + pyb * s_M0y[c + 1];
                uint32_t cp = (uint32_t)(16 * wc + 4 * nt + tcq);
                stg32[(uint32_t)ra * 64u + (cp ^ (((uint32_t)ra & 7u) << 2))] =
                    h2u(__floats2half2_rn(v0, v1));
                stg32[(uint32_t)rb * 64u + (cp ^ (((uint32_t)rb & 7u) << 2))] =
                    h2u(__floats2half2_rn(v2, v3));
            }
        }
        __syncthreads();

#pragma unroll 4
        for (int r = grp * 16; r < grp * 16 + 16; r++) {
            int node = nb + r;
            if (node < NODES) {
                uint32_t hv = stg32[(uint32_t)r * 64u +
                                    ((uint32_t)wcp ^ (((uint32_t)r & 7u) << 2))];
                *(uint32_t*)&g_y0[(size_t)node * CH + wcc] = hv;
                __half2 h;
                memcpy(&h, &hv, 4);
                float2 f = __half22float2(h);
                as0 += f.x; aq0 += f.x * f.x;
                as1 += f.y; aq1 += f.y * f.y;
            }
        }
        __syncthreads();
    }
    ((float4*)sm)[tid] = make_float4(as0, aq0, as1, aq1);
    __syncthreads();
    if (tid < 64) {
        float4 a = ((float4*)sm)[tid], b = ((float4*)sm)[tid + 64];
        float4 cc = ((float4*)sm)[tid + 128], d = ((float4*)sm)[tid + 192];
        int c = tid * 2;
        atomicAdd(&g_sum[0][c],     a.x + b.x + cc.x + d.x);
        atomicAdd(&g_sq[0][c],      a.y + b.y + cc.y + d.y);
        atomicAdd(&g_sum[0][c + 1], a.z + b.z + cc.z + d.z);
        atomicAdd(&g_sq[0][c + 1],  a.w + b.w + cc.w + d.w);
    }
    grid_sync(0);

    // ---- swap to W1 + BN0 scale/shift + bias1 ----
    {
        const char* wsrc = (const char*)g_Wimg[1];
        uint32_t wdst = smem_u32(Wt);
#pragma unroll
        for (int i = 0; i < 8; i++) {
            uint32_t off = (uint32_t)(tid + 256 * i) * 16u;
            asm volatile("cp.async.cg.shared.global [%0], [%1], 16;"
                         :: "r"(wdst + off), "l"(wsrc + off));
        }
        asm volatile("cp.async.commit_group;");
    }
    if (tid < CH) {
        s_B[tid] = bias1[tid];
        float mu = g_sum[0][tid] * (1.f / NODES);
        float var = g_sq[0][tid] * (1.f / NODES) - mu * mu;
        float sc = g0[tid] * rsqrtf(var + 1e-5f);
        s_sc[tid] = sc;
        s_sh[tid] = bb0[tid] - mu * sc;
    }
    as0 = 0.f; aq0 = 0.f; as1 = 0.f; aq1 = 0.f;
    asm volatile("cp.async.wait_group 0;");
    __syncthreads();

    // =============== PHASE B: layer 1 ===============
#pragma unroll 1
    for (int tile = blockIdx.x; tile < NBLK; tile += PGRID) {
        int nb = tile * TM;
#pragma unroll
        for (int i = 0; i < 4; i++) {
            int u = tid + 256 * i;
            int row = u >> 4;
            int chunk = u & 15;
            int gn = nb + row;
            uint4 packed = make_uint4(0, 0, 0, 0);
            if (gn < NODES) {
                uint4 raw = *(const uint4*)&g_y0[(size_t)gn * CH + chunk * 8];
                uint32_t rr[4] = {raw.x, raw.y, raw.z, raw.w};
                uint32_t oo[4];
#pragma unroll
                for (int j = 0; j < 4; j++) {
                    __half2 h;
                    memcpy(&h, &rr[j], 4);
                    float2 f = __half22float2(h);
                    int c = chunk * 8 + 2 * j;
                    float a0 = elu_fast(f.x * s_sc[c] + s_sh[c]);
                    float a1 = elu_fast(f.y * s_sc[c + 1] + s_sh[c + 1]);
                    oo[j] = h2u(__floats2half2_rn(a0, a1));
                }
                packed = make_uint4(oo[0], oo[1], oo[2], oo[3]);
            }
            *(uint4*)(At + swz((uint32_t)row, (uint32_t)chunk)) = packed;
        }
        __syncthreads();

        float C[2][4][4];
#pragma unroll
        for (int mt = 0; mt < 2; mt++)
#pragma unroll
            for (int n = 0; n < 4; n++)
#pragma unroll
                for (int j = 0; j < 4; j++) C[mt][n][j] = 0.f;
#pragma unroll
        for (int ks = 0; ks < 8; ks++) {
            uint32_t asw = (((2 * ks + aSel) ^ la7) << 4);
            uint32_t ah[2][4];
#pragma unroll
            for (int mt = 0; mt < 2; mt++) {
                uint32_t ar = (r0base + 16 * mt) * 256u + asw;
                ldsm4(ah[mt][0], ah[mt][1], ah[mt][2], ah[mt][3], baseA + ar);
            }
            uint32_t bsw = (((2 * ks + bSel) ^ la7) << 4);
#pragma unroll
            for (int np = 0; np < 2; np++) {
                uint32_t boff = bRow + np * 4096 + bsw;
                uint32_t w0, w1, w2, w3;
                ldsm4(w0, w1, w2, w3, baseW + boff);
#pragma unroll
                for (int mt = 0; mt < 2; mt++) {
                    mma_f16(C[mt][2 * np],     ah[mt][0], ah[mt][1], ah[mt][2], ah[mt][3], w0, w1);
                    mma_f16(C[mt][2 * np + 1], ah[mt][0], ah[mt][1], ah[mt][2], ah[mt][3], w2, w3);
                }
            }
        }
        __syncthreads();

#pragma unroll
        for (int mt = 0; mt < 2; mt++) {
            int ra = 32 * wr + 16 * mt + tr;
            int rb = ra + 8;
#pragma unroll
            for (int nt = 0; nt < 4; nt++) {
                int c = 32 * wc + 8 * nt + 2 * tcq;
                float v0 = C[mt][nt][0] + s_B[c];
                float v1 = C[mt][nt][1] + s_B[c + 1];
                float v2 = C[mt][nt][2] + s_B[c];
                float v3 = C[mt][nt][3] + s_B[c + 1];
                uint32_t cp = (uint32_t)(16 * wc + 4 * nt + tcq);
                stg32[(uint32_t)ra * 64u + (cp ^ (((uint32_t)ra & 7u) << 2))] =
                    h2u(__floats2half2_rn(v0, v1));
                stg32[(uint32_t)rb * 64u + (cp ^ (((uint32_t)rb & 7u) << 2))] =
                    h2u(__floats2half2_rn(v2, v3));
            }
        }
        __syncthreads();

#pragma unroll 4
        for (int r = grp * 16; r < grp * 16 + 16; r++) {
            int node = nb + r;
            if (node < NODES) {
                uint32_t hv = stg32[(uint32_t)r * 64u +
                                    ((uint32_t)wcp ^ (((uint32_t)r & 7u) << 2))];
                *(uint32_t*)&g_y1[(size_t)node * CH + wcc] = hv;
                __half2 h;
                memcpy(&h, &hv, 4);
                float2 f = __half22float2(h);
                as0 += f.x; aq0 += f.x * f.x;
                as1 += f.y; aq1 += f.y * f.y;
            }
        }
        __syncthreads();
    }
    ((float4*)sm)[tid] = make_float4(as0, aq0, as1, aq1);
    __syncthreads();
    if (tid < 64) {
        float4 a = ((float4*)sm)[tid], b = ((float4*)sm)[tid + 64];
        float4 cc = ((float4*)sm)[tid + 128], d = ((float4*)sm)[tid + 192];
        int c = tid * 2;
        atomicAdd(&g_sum[1][c],     a.x + b.x + cc.x + d.x);
        atomicAdd(&g_sq[1][c],      a.y + b.y + cc.y + d.y);
        atomicAdd(&g_sum[1][c + 1], a.z + b.z + cc.z + d.z);
        atomicAdd(&g_sq[1][c + 1],  a.w + b.w + cc.w + d.w);
    }
    grid_sync(1);

    // =============== PHASE C: pool over own tiles ===============
    {
        float mu0 = g_sum[1][wcc] * (1.f / NODES);
        float va0 = g_sq[1][wcc] * (1.f / NODES) - mu0 * mu0;
        float sc0 = g1[wcc] * rsqrtf(va0 + 1e-5f);
        float sh0 = bb1[wcc] - mu0 * sc0;
        float mu1 = g_sum[1][wcc + 1] * (1.f / NODES);
        float va1 = g_sq[1][wcc + 1] * (1.f / NODES) - mu1 * mu1;
        float sc1 = g1[wcc + 1] * rsqrtf(va1 + 1e-5f);
        float sh1 = bb1[wcc + 1] - mu1 * sc1;

#pragma unroll 1
        for (int tile = blockIdx.x; tile < NBLK; tile += PGRID) {
            int nb = tile * TM;
            int gcur = -1;
            float p0 = 0.f, p1 = 0.f;
#pragma unroll 4
            for (int r = grp * 16; r < grp * 16 + 16; r++) {
                int node = nb + r;
                if (node >= NODES) break;
                int gg = node / NPG;
                if (gg != gcur) {
                    if (gcur >= 0) {
                        atomicAdd(&g_pool[gcur * CH + wcc], p0);
                        atomicAdd(&g_pool[gcur * CH + wcc + 1], p1);
                    }
                    gcur = gg; p0 = 0.f; p1 = 0.f;
                }
                uint32_t hv = *(const uint32_t*)&g_y1[(size_t)node * CH + wcc];
                __half2 h;
                memcpy(&h, &hv, 4);
                float2 f = __half22float2(h);
                p0 += elu_fast(f.x * sc0 + sh0);
                p1 += elu_fast(f.y * sc1 + sh1);
            }
            if (gcur >= 0) {
                atomicAdd(&g_pool[gcur * CH + wcc], p0);
                atomicAdd(&g_pool[gcur * CH + wcc + 1], p1);
            }
        }
    }
}

// ---- FC: 8 threads per output, float4 loads, shuffle reduce ----
__global__ __launch_bounds__(512) void k_fc(const float* __restrict__ fcW,
                                            const float* __restrict__ fcb,
                                            float* __restrict__ out) {
    int g = blockIdx.x;
    int o = threadIdx.x >> 3;      // 0..63
    int part = threadIdx.x & 7;    // 0..7
    const float4* pool4 = (const float4*)&g_pool[g * CH];
    const float4* w4 = (const float4*)&fcW[o * CH];
    float s = 0.f;
#pragma unroll
    for (int i = 0; i < 4; i++) {
        int idx = part + 8 * i;    // 0..31 float4 indices
        float4 p = pool4[idx];
        float4 w = w4[idx];
        s += p.x * w.x + p.y * w.y + p.z * w.z + p.w * w.w;
    }
#pragma unroll
    for (int m = 1; m < 8; m <<= 1) s += __shfl_xor_sync(0xffffffff, s, m);
    if (part == 0) out[g * OUTD + o] = s * (1.f / NPG) + fcb[o];
}

extern "C" void kernel_launch(void* const* d_in, const int* in_sizes, int n_in,
                              void* d_out, int out_size) {
    const float* x   = (const float*)d_in[0];
    const float* peW = (const float*)d_in[3];
    const float* peB = (const float*)d_in[4];
    const float* W0  = (const float*)d_in[5];
    const float* b0  = (const float*)d_in[8];
    const float* g0  = (const float*)d_in[9];
    const float* bb0 = (const float*)d_in[10];
    const float* W1  = (const float*)d_in[11];
    const float* b1  = (const float*)d_in[14];
    const float* g1  = (const float*)d_in[15];
    const float* bb1 = (const float*)d_in[16];
    const float* fcW = (const float*)d_in[17];
    const float* fcb = (const float*)d_in[18];
    float* out = (float*)d_out;

    static bool once = false;
    if (!once) {
        cudaFuncSetAttribute(k_fused, cudaFuncAttributeMaxDynamicSharedMemorySize, DSMEM);
        once = true;
    }

    k_prep<<<128, 256>>>(peW, peB, W0, b0, W1);
    k_fused<<<PGRID, 256, DSMEM>>>(x, b1, g0, bb0, g1, bb1);
    k_fc<<<GRAPHS, 512>>>(fcW, fcb, out);
}

// round 15
// speedup vs baseline: 1.1531x; 1.0171x over previous
#include <cuda_runtime.h>
#include <cuda_fp16.h>
#include <math.h>
#include <stdint.h>

#define NODES 100000
#define GRAPHS 100
#define NPG 1000
#define CH 128
#define OUTD 64
#define POSD 16
#define TM 64
#define NBLK ((NODES + TM - 1) / TM)   // 1563
#define PGRID 521                      // 521*3 == 1563; single wave (<= 4*148)
#define DSMEM 49152                    // At/stage 16K | Wt 32K

// ---- device-global scratch ----
__device__ __half g_y0[(size_t)NODES * CH];
__device__ __half g_y1[(size_t)NODES * CH];
__device__ unsigned char g_Wimg[2][32768];
__device__ float g_M0[2 * CH];
__device__ float g_beff0[CH];
__device__ float g_sum[2][CH];
__device__ float g_sq[2][CH];
__device__ float g_pool[GRAPHS * CH];
__device__ volatile unsigned g_bar[3];

__device__ __forceinline__ uint32_t smem_u32(const void* p) {
    uint32_t a;
    asm("{ .reg .u64 t; cvta.to.shared.u64 t, %1; cvt.u32.u64 %0, t; }" : "=r"(a) : "l"(p));
    return a;
}
__device__ __forceinline__ uint32_t swz(uint32_t row, uint32_t chunk) {
    return row * 256u + ((chunk ^ (row & 7u)) << 4);
}
__device__ __forceinline__ void ldsm4(uint32_t& r0, uint32_t& r1, uint32_t& r2, uint32_t& r3,
                                      uint32_t addr) {
    asm volatile("ldmatrix.sync.aligned.m8n8.x4.shared.b16 {%0,%1,%2,%3}, [%4];"
                 : "=r"(r0), "=r"(r1), "=r"(r2), "=r"(r3) : "r"(addr));
}
__device__ __forceinline__ void mma_f16(float* c, uint32_t a0, uint32_t a1, uint32_t a2,
                                        uint32_t a3, uint32_t b0, uint32_t b1) {
    asm volatile(
        "mma.sync.aligned.m16n8k16.row.col.f32.f16.f16.f32 "
        "{%0,%1,%2,%3}, {%4,%5,%6,%7}, {%8,%9}, {%0,%1,%2,%3};"
        : "+f"(c[0]), "+f"(c[1]), "+f"(c[2]), "+f"(c[3])
        : "r"(a0), "r"(a1), "r"(a2), "r"(a3), "r"(b0), "r"(b1));
}
__device__ __forceinline__ uint32_t h2u(__half2 h) {
    uint32_t u;
    memcpy(&u, &h, 4);
    return u;
}
__device__ __forceinline__ float elu_fast(float x) {
    return (x > 0.f) ? x : (__expf(x) - 1.f);
}
__device__ __forceinline__ void grid_sync(int ph) {
    __syncthreads();
    if (threadIdx.x == 0) {
        __threadfence();
        atomicAdd((unsigned*)&g_bar[ph], 1u);
        while (g_bar[ph] < PGRID) { }
        __threadfence();
    }
    __syncthreads();
}

// ---- prep: vectorized W image build + accumulator reset + PE fold ----
__global__ void k_prep(const float* __restrict__ peW, const float* __restrict__ peB,
                       const float* __restrict__ W0, const float* __restrict__ b0,
                       const float* __restrict__ W1) {
    int t = blockIdx.x * blockDim.x + threadIdx.x;
    int stride = gridDim.x * blockDim.x;
    if (t < 3) g_bar[t] = 0u;
    for (int i = t; i < GRAPHS * CH; i += stride) g_pool[i] = 0.f;
    if (t < CH) {
        g_sum[0][t] = 0.f; g_sum[1][t] = 0.f;
        g_sq[0][t] = 0.f;  g_sq[1][t] = 0.f;
    }
    // W image: 2 layers x 128 c x 16 chunks = 4096 vector tasks
    if (t < 4096) {
        int layer = t >> 11;
        int u = t & 2047;
        int c = u >> 4;
        int chunk = u & 15;
        int wstride = layer ? CH : 144;
        const float4* src = (const float4*)(layer ? W1 : W0) + ((size_t)c * wstride + chunk * 8) / 4;
        float4 p0 = src[0], p1 = src[1];
        uint4 packed;
        packed.x = h2u(__floats2half2_rn(p0.x, p0.y));
        packed.y = h2u(__floats2half2_rn(p0.z, p0.w));
        packed.z = h2u(__floats2half2_rn(p1.x, p1.y));
        packed.w = h2u(__floats2half2_rn(p1.z, p1.w));
        *(uint4*)(g_Wimg[layer] + swz((uint32_t)c, (uint32_t)chunk)) = packed;
    }
    if (blockIdx.x == 0 && threadIdx.x < CH) {
        int c = threadIdx.x;
        float m0 = 0.f, m1 = 0.f, be = 0.f;
#pragma unroll
        for (int k = 0; k < POSD; k++) {
            float w = W0[c * 144 + 128 + k];
            m0 += peW[2 * k] * w;
            m1 += peW[2 * k + 1] * w;
            be += peB[k] * w;
        }
        g_M0[c] = m0; g_M0[CH + c] = m1;
        g_beff0[c] = be + b0[c];
    }
}

// ---- fused persistent kernel: layer0 | sync | layer1 | sync | pool | sync | fc ----
__global__ __launch_bounds__(256, 4) void k_fused(const float* __restrict__ xin,
                                                  const float* __restrict__ bias1,
                                                  const float* __restrict__ g0,
                                                  const float* __restrict__ bb0,
                                                  const float* __restrict__ g1,
                                                  const float* __restrict__ bb1,
                                                  const float* __restrict__ fcW,
                                                  const float* __restrict__ fcb,
                                                  float* __restrict__ out) {
    extern __shared__ char sm[];
    char* At = sm;
    char* Wt = sm + 16384;
    uint32_t* stg32 = (uint32_t*)sm;

    __shared__ float s_B[CH], s_M0x[CH], s_M0y[CH], s_sc[CH], s_sh[CH];

    int tid = threadIdx.x;
    int wid = tid >> 5;
    int lane = tid & 31;

    int wr = wid >> 2;
    int wc = wid & 3;
    uint32_t la7 = lane & 7;
    uint32_t aSel = (uint32_t)(lane >> 4);
    uint32_t r0base = (uint32_t)(32 * wr + (lane & 15));
    uint32_t bRow = (uint32_t)(32 * wc + (lane & 7) + ((lane >> 4) << 3)) * 256u;
    uint32_t bSel = (uint32_t)((lane >> 3) & 1);
    uint32_t baseA = smem_u32(At), baseW = smem_u32(Wt);
    int tr = lane >> 2;
    int tcq = lane & 3;
    int wcp = tid & 63;
    int wcc = wcp * 2;
    int grp = tid >> 6;

    // ---- W0 image + constants ----
    {
        const char* wsrc = (const char*)g_Wimg[0];
        uint32_t wdst = smem_u32(Wt);
#pragma unroll
        for (int i = 0; i < 8; i++) {
            uint32_t off = (uint32_t)(tid + 256 * i) * 16u;
            asm volatile("cp.async.cg.shared.global [%0], [%1], 16;"
                         :: "r"(wdst + off), "l"(wsrc + off));
        }
        asm volatile("cp.async.commit_group;");
    }
    if (tid < CH) {
        s_B[tid] = g_beff0[tid];
        s_M0x[tid] = g_M0[tid];
        s_M0y[tid] = g_M0[CH + tid];
    }
    float as0 = 0.f, aq0 = 0.f, as1 = 0.f, aq1 = 0.f;
    asm volatile("cp.async.wait_group 0;");
    __syncthreads();

    // =============== PHASE A: layer 0 ===============
#pragma unroll 1
    for (int tile = blockIdx.x; tile < NBLK; tile += PGRID) {
        int nb = tile * TM;
#pragma unroll
        for (int i = 0; i < 4; i++) {
            int u = tid + 256 * i;
            int row = u >> 4;
            int chunk = u & 15;
            int gn = nb + row;
            uint4 packed = make_uint4(0, 0, 0, 0);
            if (gn < NODES) {
                const float4* src4 = (const float4*)xin;
                float4 p0 = src4[(size_t)gn * 32 + chunk * 2];
                float4 p1 = src4[(size_t)gn * 32 + chunk * 2 + 1];
                packed.x = h2u(__floats2half2_rn(p0.x, p0.y));
                packed.y = h2u(__floats2half2_rn(p0.z, p0.w));
                packed.z = h2u(__floats2half2_rn(p1.x, p1.y));
                packed.w = h2u(__floats2half2_rn(p1.z, p1.w));
            }
            *(uint4*)(At + swz((uint32_t)row, (uint32_t)chunk)) = packed;
        }
        __syncthreads();

        float C[2][4][4];
#pragma unroll
        for (int mt = 0; mt < 2; mt++)
#pragma unroll
            for (int n = 0; n < 4; n++)
#pragma unroll
                for (int j = 0; j < 4; j++) C[mt][n][j] = 0.f;
#pragma unroll
        for (int ks = 0; ks < 8; ks++) {
            uint32_t asw = (((2 * ks + aSel) ^ la7) << 4);
            uint32_t ah[2][4];
#pragma unroll
            for (int mt = 0; mt < 2; mt++) {
                uint32_t ar = (r0base + 16 * mt) * 256u + asw;
                ldsm4(ah[mt][0], ah[mt][1], ah[mt][2], ah[mt][3], baseA + ar);
            }
            uint32_t bsw = (((2 * ks + bSel) ^ la7) << 4);
#pragma unroll
            for (int np = 0; np < 2; np++) {
                uint32_t boff = bRow + np * 4096 + bsw;
                uint32_t w0, w1, w2, w3;
                ldsm4(w0, w1, w2, w3, baseW + boff);
#pragma unroll
                for (int mt = 0; mt < 2; mt++) {
                    mma_f16(C[mt][2 * np],     ah[mt][0], ah[mt][1], ah[mt][2], ah[mt][3], w0, w1);
                    mma_f16(C[mt][2 * np + 1], ah[mt][0], ah[mt][1], ah[mt][2], ah[mt][3], w2, w3);
                }
            }
        }
        __syncthreads();

#pragma unroll
        for (int mt = 0; mt < 2; mt++) {
            int ra = 32 * wr + 16 * mt + tr;
            int rb = ra + 8;
            int na = nb + ra, nbo = nb + rb;
            int la = na - (na / NPG) * NPG;
            int lb = nbo - (nbo / NPG) * NPG;
            float pxa = (float)(la >> 5) * (1.f / 31.f);
            float pya = (float)(la & 31) * (1.f / 31.f);
            float pxb = (float)(lb >> 5) * (1.f / 31.f);
            float pyb = (float)(lb & 31) * (1.f / 31.f);
#pragma unroll
            for (int nt = 0; nt < 4; nt++) {
                int c = 32 * wc + 8 * nt + 2 * tcq;
                float v0 = C[mt][nt][0] + s_B[c]     + pxa * s_M0x[c]     + pya * s_M0y[c];
                float v1 = C[mt][nt][1] + s_B[c + 1] + pxa * s_M0x[c + 1] + pya * s_M0y[c + 1];
                float v2 = C[mt][nt][2] + s_B[c]     + pxb * s_M0x[c]     + pyb * s_M0y[c];
                float v3 = C[mt][nt][3] + s_B[c + 1] + pxb * s_M0x[c + 1] + pyb * s_M0y[c + 1];
                uint32_t cp = (uint32_t)(16 * wc + 4 * nt + tcq);
                stg32[(uint32_t)ra * 64u + (cp ^ (((uint32_t)ra & 7u) << 2))] =
                    h2u(__floats2half2_rn(v0, v1));
                stg32[(uint32_t)rb * 64u + (cp ^ (((uint32_t)rb & 7u) << 2))] =
                    h2u(__floats2half2_rn(v2, v3));
            }
        }
        __syncthreads();

#pragma unroll 4
        for (int r = grp * 16; r < grp * 16 + 16; r++) {
            int node = nb + r;
            if (node < NODES) {
                uint32_t hv = stg32[(uint32_t)r * 64u +
                                    ((uint32_t)wcp ^ (((uint32_t)r & 7u) << 2))];
                *(uint32_t*)&g_y0[(size_t)node * CH + wcc] = hv;
                __half2 h;
                memcpy(&h, &hv, 4);
                float2 f = __half22float2(h);
                as0 += f.x; aq0 += f.x * f.x;
                as1 += f.y; aq1 += f.y * f.y;
            }
        }
        __syncthreads();
    }
    ((float4*)sm)[tid] = make_float4(as0, aq0, as1, aq1);
    __syncthreads();
    if (tid < 64) {
        float4 a = ((float4*)sm)[tid], b = ((float4*)sm)[tid + 64];
        float4 cc = ((float4*)sm)[tid + 128], d = ((float4*)sm)[tid + 192];
        int c = tid * 2;
        atomicAdd(&g_sum[0][c],     a.x + b.x + cc.x + d.x);
        atomicAdd(&g_sq[0][c],      a.y + b.y + cc.y + d.y);
        atomicAdd(&g_sum[0][c + 1], a.z + b.z + cc.z + d.z);
        atomicAdd(&g_sq[0][c + 1],  a.w + b.w + cc.w + d.w);
    }
    grid_sync(0);

    // ---- swap to W1 + BN0 scale/shift + bias1 ----
    {
        const char* wsrc = (const char*)g_Wimg[1];
        uint32_t wdst = smem_u32(Wt);
#pragma unroll
        for (int i = 0; i < 8; i++) {
            uint32_t off = (uint32_t)(tid + 256 * i) * 16u;
            asm volatile("cp.async.cg.shared.global [%0], [%1], 16;"
                         :: "r"(wdst + off), "l"(wsrc + off));
        }
        asm volatile("cp.async.commit_group;");
    }
    if (tid < CH) {
        s_B[tid] = bias1[tid];
        float mu = g_sum[0][tid] * (1.f / NODES);
        float var = g_sq[0][tid] * (1.f / NODES) - mu * mu;
        float sc = g0[tid] * rsqrtf(var + 1e-5f);
        s_sc[tid] = sc;
        s_sh[tid] = bb0[tid] - mu * sc;
    }
    as0 = 0.f; aq0 = 0.f; as1 = 0.f; aq1 = 0.f;
    asm volatile("cp.async.wait_group 0;");
    __syncthreads();

    // =============== PHASE B: layer 1 ===============
#pragma unroll 1
    for (int tile = blockIdx.x; tile < NBLK; tile += PGRID) {
        int nb = tile * TM;
#pragma unroll
        for (int i = 0; i < 4; i++) {
            int u = tid + 256 * i;
            int row = u >> 4;
            int chunk = u & 15;
            int gn = nb + row;
            uint4 packed = make_uint4(0, 0, 0, 0);
            if (gn < NODES) {
                uint4 raw = *(const uint4*)&g_y0[(size_t)gn * CH + chunk * 8];
                uint32_t rr[4] = {raw.x, raw.y, raw.z, raw.w};
                uint32_t oo[4];
#pragma unroll
                for (int j = 0; j < 4; j++) {
                    __half2 h;
                    memcpy(&h, &rr[j], 4);
                    float2 f = __half22float2(h);
                    int c = chunk * 8 + 2 * j;
                    float a0 = elu_fast(f.x * s_sc[c] + s_sh[c]);
                    float a1 = elu_fast(f.y * s_sc[c + 1] + s_sh[c + 1]);
                    oo[j] = h2u(__floats2half2_rn(a0, a1));
                }
                packed = make_uint4(oo[0], oo[1], oo[2], oo[3]);
            }
            *(uint4*)(At + swz((uint32_t)row, (uint32_t)chunk)) = packed;
        }
        __syncthreads();

        float C[2][4][4];
#pragma unroll
        for (int mt = 0; mt < 2; mt++)
#pragma unroll
            for (int n = 0; n < 4; n++)
#pragma unroll
                for (int j = 0; j < 4; j++) C[mt][n][j] = 0.f;
#pragma unroll
        for (int ks = 0; ks < 8; ks++) {
            uint32_t asw = (((2 * ks + aSel) ^ la7) << 4);
            uint32_t ah[2][4];
#pragma unroll
            for (int mt = 0; mt < 2; mt++) {
                uint32_t ar = (r0base + 16 * mt) * 256u + asw;
                ldsm4(ah[mt][0], ah[mt][1], ah[mt][2], ah[mt][3], baseA + ar);
            }
            uint32_t bsw = (((2 * ks + bSel) ^ la7) << 4);
#pragma unroll
            for (int np = 0; np < 2; np++) {
                uint32_t boff = bRow + np * 4096 + bsw;
                uint32_t w0, w1, w2, w3;
                ldsm4(w0, w1, w2, w3, baseW + boff);
#pragma unroll
                for (int mt = 0; mt < 2; mt++) {
                    mma_f16(C[mt][2 * np],     ah[mt][0], ah[mt][1], ah[mt][2], ah[mt][3], w0, w1);
                    mma_f16(C[mt][2 * np + 1], ah[mt][0], ah[mt][1], ah[mt][2], ah[mt][3], w2, w3);
                }
            }
        }
        __syncthreads();

#pragma unroll
        for (int mt = 0; mt < 2; mt++) {
            int ra = 32 * wr + 16 * mt + tr;
            int rb = ra + 8;
#pragma unroll
            for (int nt = 0; nt < 4; nt++) {
                int c = 32 * wc + 8 * nt + 2 * tcq;
                float v0 = C[mt][nt][0] + s_B[c];
                float v1 = C[mt][nt][1] + s_B[c + 1];
                float v2 = C[mt][nt][2] + s_B[c];
                float v3 = C[mt][nt][3] + s_B[c + 1];
                uint32_t cp = (uint32_t)(16 * wc + 4 * nt + tcq);
                stg32[(uint32_t)ra * 64u + (cp ^ (((uint32_t)ra & 7u) << 2))] =
                    h2u(__floats2half2_rn(v0, v1));
                stg32[(uint32_t)rb * 64u + (cp ^ (((uint32_t)rb & 7u) << 2))] =
                    h2u(__floats2half2_rn(v2, v3));
            }
        }
        __syncthreads();

#pragma unroll 4
        for (int r = grp * 16; r < grp * 16 + 16; r++) {
            int node = nb + r;
            if (node < NODES) {
                uint32_t hv = stg32[(uint32_t)r * 64u +
                                    ((uint32_t)wcp ^ (((uint32_t)r & 7u) << 2))];
                *(uint32_t*)&g_y1[(size_t)node * CH + wcc] = hv;
                __half2 h;
                memcpy(&h, &hv, 4);
                float2 f = __half22float2(h);
                as0 += f.x; aq0 += f.x * f.x;
                as1 += f.y; aq1 += f.y * f.y;
            }
        }
        __syncthreads();
    }
    ((float4*)sm)[tid] = make_float4(as0, aq0, as1, aq1);
    __syncthreads();
    if (tid < 64) {
        float4 a = ((float4*)sm)[tid], b = ((float4*)sm)[tid + 64];
        float4 cc = ((float4*)sm)[tid + 128], d = ((float4*)sm)[tid + 192];
        int c = tid * 2;
        atomicAdd(&g_sum[1][c],     a.x + b.x + cc.x + d.x);
        atomicAdd(&g_sq[1][c],      a.y + b.y + cc.y + d.y);
        atomicAdd(&g_sum[1][c + 1], a.z + b.z + cc.z + d.z);
        atomicAdd(&g_sq[1][c + 1],  a.w + b.w + cc.w + d.w);
    }
    grid_sync(1);

    // =============== PHASE C: pool over own tiles ===============
    {
        float mu0 = g_sum[1][wcc] * (1.f / NODES);
        float va0 = g_sq[1][wcc] * (1.f / NODES) - mu0 * mu0;
        float sc0 = g1[wcc] * rsqrtf(va0 + 1e-5f);
        float sh0 = bb1[wcc] - mu0 * sc0;
        float mu1 = g_sum[1][wcc + 1] * (1.f / NODES);
        float va1 = g_sq[1][wcc + 1] * (1.f / NODES) - mu1 * mu1;
        float sc1 = g1[wcc + 1] * rsqrtf(va1 + 1e-5f);
        float sh1 = bb1[wcc + 1] - mu1 * sc1;

#pragma unroll 1
        for (int tile = blockIdx.x; tile < NBLK; tile += PGRID) {
            int nb = tile * TM;
            int gcur = -1;
            float p0 = 0.f, p1 = 0.f;
#pragma unroll 4
            for (int r = grp * 16; r < grp * 16 + 16; r++) {
                int node = nb + r;
                if (node >= NODES) break;
                int gg = node / NPG;
                if (gg != gcur) {
                    if (gcur >= 0) {
                        atomicAdd(&g_pool[gcur * CH + wcc], p0);
                        atomicAdd(&g_pool[gcur * CH + wcc + 1], p1);
                    }
                    gcur = gg; p0 = 0.f; p1 = 0.f;
                }
                uint32_t hv = *(const uint32_t*)&g_y1[(size_t)node * CH + wcc];
                __half2 h;
                memcpy(&h, &hv, 4);
                float2 f = __half22float2(h);
                p0 += elu_fast(f.x * sc0 + sh0);
                p1 += elu_fast(f.y * sc1 + sh1);
            }
            if (gcur >= 0) {
                atomicAdd(&g_pool[gcur * CH + wcc], p0);
                atomicAdd(&g_pool[gcur * CH + wcc + 1], p1);
            }
        }
    }
    grid_sync(2);

    // =============== PHASE D: FC (CTAs 0..99, one graph each) ===============
    if (blockIdx.x < GRAPHS) {
        int g = blockIdx.x;
        int o = tid >> 2;          // 0..63
        int part = tid & 3;        // 0..3
        const float4* pool4 = (const float4*)&g_pool[g * CH];
        const float4* w4 = (const float4*)&fcW[o * CH];
        float s = 0.f;
#pragma unroll
        for (int i = 0; i < 8; i++) {
            int idx = part + 4 * i;    // 0..31
            float4 p = pool4[idx];
            float4 w = w4[idx];
            s += p.x * w.x + p.y * w.y + p.z * w.z + p.w * w.w;
        }
#pragma unroll
        for (int m = 1; m < 4; m <<= 1) s += __shfl_xor_sync(0xffffffff, s, m);
        if (part == 0) out[g * OUTD + o] = s * (1.f / NPG) + fcb[o];
    }
}

extern "C" void kernel_launch(void* const* d_in, const int* in_sizes, int n_in,
                              void* d_out, int out_size) {
    const float* x   = (const float*)d_in[0];
    const float* peW = (const float*)d_in[3];
    const float* peB = (const float*)d_in[4];
    const float* W0  = (const float*)d_in[5];
    const float* b0  = (const float*)d_in[8];
    const float* g0  = (const float*)d_in[9];
    const float* bb0 = (const float*)d_in[10];
    const float* W1  = (const float*)d_in[11];
    const float* b1  = (const float*)d_in[14];
    const float* g1  = (const float*)d_in[15];
    const float* bb1 = (const float*)d_in[16];
    const float* fcW = (const float*)d_in[17];
    const float* fcb = (const float*)d_in[18];
    float* out = (float*)d_out;

    static bool once = false;
    if (!once) {
        cudaFuncSetAttribute(k_fused, cudaFuncAttributeMaxDynamicSharedMemorySize, DSMEM);
        once = true;
    }

    k_prep<<<64, 256>>>(peW, peB, W0, b0, W1);
    k_fused<<<PGRID, 256, DSMEM>>>(x, b1, g0, bb0, g1, bb1, fcW, fcb, out);
}

// round 16
// speedup vs baseline: 1.1751x; 1.0191x over previous
#include <cuda_runtime.h>
#include <cuda_fp16.h>
#include <math.h>
#include <stdint.h>

#define NODES 100000
#define GRAPHS 100
#define NPG 1000
#define CH 128
#define OUTD 64
#define POSD 16
#define TM 64
#define NBLK ((NODES + TM - 1) / TM)   // 1563
#define PGRID 592                      // 4 CTAs/SM x 148 SMs: exact single-wave fill
#define DSMEM 49152                    // At/stage 16K | Wt 32K

// ---- device-global scratch ----
__device__ __half g_y0[(size_t)NODES * CH];
__device__ __half g_y1[(size_t)NODES * CH];
__device__ unsigned char g_Wimg[2][32768];
__device__ float g_M0[2 * CH];
__device__ float g_beff0[CH];
__device__ float g_sum[2][CH];
__device__ float g_sq[2][CH];
__device__ float g_pool[GRAPHS * CH];
__device__ volatile unsigned g_bar[3];

__device__ __forceinline__ uint32_t smem_u32(const void* p) {
    uint32_t a;
    asm("{ .reg .u64 t; cvta.to.shared.u64 t, %1; cvt.u32.u64 %0, t; }" : "=r"(a) : "l"(p));
    return a;
}
__device__ __forceinline__ uint32_t swz(uint32_t row, uint32_t chunk) {
    return row * 256u + ((chunk ^ (row & 7u)) << 4);
}
__device__ __forceinline__ void ldsm4(uint32_t& r0, uint32_t& r1, uint32_t& r2, uint32_t& r3,
                                      uint32_t addr) {
    asm volatile("ldmatrix.sync.aligned.m8n8.x4.shared.b16 {%0,%1,%2,%3}, [%4];"
                 : "=r"(r0), "=r"(r1), "=r"(r2), "=r"(r3) : "r"(addr));
}
__device__ __forceinline__ void mma_f16(float* c, uint32_t a0, uint32_t a1, uint32_t a2,
                                        uint32_t a3, uint32_t b0, uint32_t b1) {
    asm volatile(
        "mma.sync.aligned.m16n8k16.row.col.f32.f16.f16.f32 "
        "{%0,%1,%2,%3}, {%4,%5,%6,%7}, {%8,%9}, {%0,%1,%2,%3};"
        : "+f"(c[0]), "+f"(c[1]), "+f"(c[2]), "+f"(c[3])
        : "r"(a0), "r"(a1), "r"(a2), "r"(a3), "r"(b0), "r"(b1));
}
__device__ __forceinline__ uint32_t h2u(__half2 h) {
    uint32_t u;
    memcpy(&u, &h, 4);
    return u;
}
__device__ __forceinline__ float elu_fast(float x) {
    return (x > 0.f) ? x : (__expf(x) - 1.f);
}
__device__ __forceinline__ void grid_sync(int ph) {
    __syncthreads();
    if (threadIdx.x == 0) {
        __threadfence();
        atomicAdd((unsigned*)&g_bar[ph], 1u);
        while (g_bar[ph] < PGRID) { }
        __threadfence();
    }
    __syncthreads();
}

// ---- prep: vectorized W image build + accumulator reset + PE fold ----
__global__ void k_prep(const float* __restrict__ peW, const float* __restrict__ peB,
                       const float* __restrict__ W0, const float* __restrict__ b0,
                       const float* __restrict__ W1) {
    int t = blockIdx.x * blockDim.x + threadIdx.x;
    int stride = gridDim.x * blockDim.x;
    if (t < 3) g_bar[t] = 0u;
    for (int i = t; i < GRAPHS * CH; i += stride) g_pool[i] = 0.f;
    if (t < CH) {
        g_sum[0][t] = 0.f; g_sum[1][t] = 0.f;
        g_sq[0][t] = 0.f;  g_sq[1][t] = 0.f;
    }
    if (t < 4096) {
        int layer = t >> 11;
        int u = t & 2047;
        int c = u >> 4;
        int chunk = u & 15;
        int wstride = layer ? CH : 144;
        const float4* src = (const float4*)(layer ? W1 : W0) + ((size_t)c * wstride + chunk * 8) / 4;
        float4 p0 = src[0], p1 = src[1];
        uint4 packed;
        packed.x = h2u(__floats2half2_rn(p0.x, p0.y));
        packed.y = h2u(__floats2half2_rn(p0.z, p0.w));
        packed.z = h2u(__floats2half2_rn(p1.x, p1.y));
        packed.w = h2u(__floats2half2_rn(p1.z, p1.w));
        *(uint4*)(g_Wimg[layer] + swz((uint32_t)c, (uint32_t)chunk)) = packed;
    }
    if (blockIdx.x == 0 && threadIdx.x < CH) {
        int c = threadIdx.x;
        float m0 = 0.f, m1 = 0.f, be = 0.f;
#pragma unroll
        for (int k = 0; k < POSD; k++) {
            float w = W0[c * 144 + 128 + k];
            m0 += peW[2 * k] * w;
            m1 += peW[2 * k + 1] * w;
            be += peB[k] * w;
        }
        g_M0[c] = m0; g_M0[CH + c] = m1;
        g_beff0[c] = be + b0[c];
    }
}

// ---- fused persistent kernel: layer0 | sync | layer1 | sync | pool | sync | fc ----
__global__ __launch_bounds__(256, 4) void k_fused(const float* __restrict__ xin,
                                                  const float* __restrict__ bias1,
                                                  const float* __restrict__ g0,
                                                  const float* __restrict__ bb0,
                                                  const float* __restrict__ g1,
                                                  const float* __restrict__ bb1,
                                                  const float* __restrict__ fcW,
                                                  const float* __restrict__ fcb,
                                                  float* __restrict__ out) {
    extern __shared__ char sm[];
    char* At = sm;
    char* Wt = sm + 16384;
    uint32_t* stg32 = (uint32_t*)sm;

    __shared__ float s_B[CH], s_M0x[CH], s_M0y[CH], s_sc[CH], s_sh[CH];

    int tid = threadIdx.x;
    int wid = tid >> 5;
    int lane = tid & 31;

    int wr = wid >> 2;
    int wc = wid & 3;
    uint32_t la7 = lane & 7;
    uint32_t aSel = (uint32_t)(lane >> 4);
    uint32_t r0base = (uint32_t)(32 * wr + (lane & 15));
    uint32_t bRow = (uint32_t)(32 * wc + (lane & 7) + ((lane >> 4) << 3)) * 256u;
    uint32_t bSel = (uint32_t)((lane >> 3) & 1);
    uint32_t baseA = smem_u32(At), baseW = smem_u32(Wt);
    int tr = lane >> 2;
    int tcq = lane & 3;
    int wcp = tid & 63;
    int wcc = wcp * 2;
    int grp = tid >> 6;

    // ---- W0 image + constants ----
    {
        const char* wsrc = (const char*)g_Wimg[0];
        uint32_t wdst = smem_u32(Wt);
#pragma unroll
        for (int i = 0; i < 8; i++) {
            uint32_t off = (uint32_t)(tid + 256 * i) * 16u;
            asm volatile("cp.async.cg.shared.global [%0], [%1], 16;"
                         :: "r"(wdst + off), "l"(wsrc + off));
        }
        asm volatile("cp.async.commit_group;");
    }
    if (tid < CH) {
        s_B[tid] = g_beff0[tid];
        s_M0x[tid] = g_M0[tid];
        s_M0y[tid] = g_M0[CH + tid];
    }
    float as0 = 0.f, aq0 = 0.f, as1 = 0.f, aq1 = 0.f;
    asm volatile("cp.async.wait_group 0;");
    __syncthreads();

    // =============== PHASE A: layer 0 ===============
#pragma unroll 1
    for (int tile = blockIdx.x; tile < NBLK; tile += PGRID) {
        int nb = tile * TM;
#pragma unroll
        for (int i = 0; i < 4; i++) {
            int u = tid + 256 * i;
            int row = u >> 4;
            int chunk = u & 15;
            int gn = nb + row;
            uint4 packed = make_uint4(0, 0, 0, 0);
            if (gn < NODES) {
                const float4* src4 = (const float4*)xin;
                float4 p0 = src4[(size_t)gn * 32 + chunk * 2];
                float4 p1 = src4[(size_t)gn * 32 + chunk * 2 + 1];
                packed.x = h2u(__floats2half2_rn(p0.x, p0.y));
                packed.y = h2u(__floats2half2_rn(p0.z, p0.w));
                packed.z = h2u(__floats2half2_rn(p1.x, p1.y));
                packed.w = h2u(__floats2half2_rn(p1.z, p1.w));
            }
            *(uint4*)(At + swz((uint32_t)row, (uint32_t)chunk)) = packed;
        }
        __syncthreads();

        float C[2][4][4];
#pragma unroll
        for (int mt = 0; mt < 2; mt++)
#pragma unroll
            for (int n = 0; n < 4; n++)
#pragma unroll
                for (int j = 0; j < 4; j++) C[mt][n][j] = 0.f;
#pragma unroll
        for (int ks = 0; ks < 8; ks++) {
            uint32_t asw = (((2 * ks + aSel) ^ la7) << 4);
            uint32_t ah[2][4];
#pragma unroll
            for (int mt = 0; mt < 2; mt++) {
                uint32_t ar = (r0base + 16 * mt) * 256u + asw;
                ldsm4(ah[mt][0], ah[mt][1], ah[mt][2], ah[mt][3], baseA + ar);
            }
            uint32_t bsw = (((2 * ks + bSel) ^ la7) << 4);
#pragma unroll
            for (int np = 0; np < 2; np++) {
                uint32_t boff = bRow + np * 4096 + bsw;
                uint32_t w0, w1, w2, w3;
                ldsm4(w0, w1, w2, w3, baseW + boff);
#pragma unroll
                for (int mt = 0; mt < 2; mt++) {
                    mma_f16(C[mt][2 * np],     ah[mt][0], ah[mt][1], ah[mt][2], ah[mt][3], w0, w1);
                    mma_f16(C[mt][2 * np + 1], ah[mt][0], ah[mt][1], ah[mt][2], ah[mt][3], w2, w3);
                }
            }
        }
        __syncthreads();

#pragma unroll
        for (int mt = 0; mt < 2; mt++) {
            int ra = 32 * wr + 16 * mt + tr;
            int rb = ra + 8;
            int na = nb + ra, nbo = nb + rb;
            int la = na - (na / NPG) * NPG;
            int lb = nbo - (nbo / NPG) * NPG;
            float pxa = (float)(la >> 5) * (1.f / 31.f);
            float pya = (float)(la & 31) * (1.f / 31.f);
            float pxb = (float)(lb >> 5) * (1.f / 31.f);
            float pyb = (float)(lb & 31) * (1.f / 31.f);
#pragma unroll
            for (int nt = 0; nt < 4; nt++) {
                int c = 32 * wc + 8 * nt + 2 * tcq;
                float v0 = C[mt][nt][0] + s_B[c]     + pxa * s_M0x[c]     + pya * s_M0y[c];
                float v1 = C[mt][nt][1] + s_B[c + 1] + pxa * s_M0x[c + 1] + pya * s_M0y[c + 1];
                float v2 = C[mt][nt][2] + s_B[c]     + pxb * s_M0x[c]     + pyb * s_M0y[c];
                float v3 = C[mt][nt][3] + s_B[c + 1] + pxb * s_M0x[c + 1] + pyb * s_M0y[c + 1];
                uint32_t cp = (uint32_t)(16 * wc + 4 * nt + tcq);
                stg32[(uint32_t)ra * 64u + (cp ^ (((uint32_t)ra & 7u) << 2))] =
                    h2u(__floats2half2_rn(v0, v1));
                stg32[(uint32_t)rb * 64u + (cp ^ (((uint32_t)rb & 7u) << 2))] =
                    h2u(__floats2half2_rn(v2, v3));
            }
        }
        __syncthreads();

#pragma unroll 4
        for (int r = grp * 16; r < grp * 16 + 16; r++) {
            int node = nb + r;
            if (node < NODES) {
                uint32_t hv = stg32[(uint32_t)r * 64u +
                                    ((uint32_t)wcp ^ (((uint32_t)r & 7u) << 2))];
                *(uint32_t*)&g_y0[(size_t)node * CH + wcc] = hv;
                __half2 h;
                memcpy(&h, &hv, 4);
                float2 f = __half22float2(h);
                as0 += f.x; aq0 += f.x * f.x;
                as1 += f.y; aq1 += f.y * f.y;
            }
        }
        __syncthreads();
    }
    ((float4*)sm)[tid] = make_float4(as0, aq0, as1, aq1);
    __syncthreads();
    if (tid < 64) {
        float4 a = ((float4*)sm)[tid], b = ((float4*)sm)[tid + 64];
        float4 cc = ((float4*)sm)[tid + 128], d = ((float4*)sm)[tid + 192];
        int c = tid * 2;
        atomicAdd(&g_sum[0][c],     a.x + b.x + cc.x + d.x);
        atomicAdd(&g_sq[0][c],      a.y + b.y + cc.y + d.y);
        atomicAdd(&g_sum[0][c + 1], a.z + b.z + cc.z + d.z);
        atomicAdd(&g_sq[0][c + 1],  a.w + b.w + cc.w + d.w);
    }
    grid_sync(0);

    // ---- swap to W1 + BN0 scale/shift + bias1 ----
    {
        const char* wsrc = (const char*)g_Wimg[1];
        uint32_t wdst = smem_u32(Wt);
#pragma unroll
        for (int i = 0; i < 8; i++) {
            uint32_t off = (uint32_t)(tid + 256 * i) * 16u;
            asm volatile("cp.async.cg.shared.global [%0], [%1], 16;"
                         :: "r"(wdst + off), "l"(wsrc + off));
        }
        asm volatile("cp.async.commit_group;");
    }
    if (tid < CH) {
        s_B[tid] = bias1[tid];
        float mu = g_sum[0][tid] * (1.f / NODES);
        float var = g_sq[0][tid] * (1.f / NODES) - mu * mu;
        float sc = g0[tid] * rsqrtf(var + 1e-5f);
        s_sc[tid] = sc;
        s_sh[tid] = bb0[tid] - mu * sc;
    }
    as0 = 0.f; aq0 = 0.f; as1 = 0.f; aq1 = 0.f;
    asm volatile("cp.async.wait_group 0;");
    __syncthreads();

    // =============== PHASE B: layer 1 ===============
#pragma unroll 1
    for (int tile = blockIdx.x; tile < NBLK; tile += PGRID) {
        int nb = tile * TM;
#pragma unroll
        for (int i = 0; i < 4; i++) {
            int u = tid + 256 * i;
            int row = u >> 4;
            int chunk = u & 15;
            int gn = nb + row;
            uint4 packed = make_uint4(0, 0, 0, 0);
            if (gn < NODES) {
                uint4 raw = *(const uint4*)&g_y0[(size_t)gn * CH + chunk * 8];
                uint32_t rr[4] = {raw.x, raw.y, raw.z, raw.w};
                uint32_t oo[4];
#pragma unroll
                for (int j = 0; j < 4; j++) {
                    __half2 h;
                    memcpy(&h, &rr[j], 4);
                    float2 f = __half22float2(h);
                    int c = chunk * 8 + 2 * j;
                    float a0 = elu_fast(f.x * s_sc[c] + s_sh[c]);
                    float a1 = elu_fast(f.y * s_sc[c + 1] + s_sh[c + 1]);
                    oo[j] = h2u(__floats2half2_rn(a0, a1));
                }
                packed = make_uint4(oo[0], oo[1], oo[2], oo[3]);
            }
            *(uint4*)(At + swz((uint32_t)row, (uint32_t)chunk)) = packed;
        }
        __syncthreads();

        float C[2][4][4];
#pragma unroll
        for (int mt = 0; mt < 2; mt++)
#pragma unroll
            for (int n = 0; n < 4; n++)
#pragma unroll
                for (int j = 0; j < 4; j++) C[mt][n][j] = 0.f;
#pragma unroll
        for (int ks = 0; ks < 8; ks++) {
            uint32_t asw = (((2 * ks + aSel) ^ la7) << 4);
            uint32_t ah[2][4];
#pragma unroll
            for (int mt = 0; mt < 2; mt++) {
                uint32_t ar = (r0base + 16 * mt) * 256u + asw;
                ldsm4(ah[mt][0], ah[mt][1], ah[mt][2], ah[mt][3], baseA + ar);
            }
            uint32_t bsw = (((2 * ks + bSel) ^ la7) << 4);
#pragma unroll
            for (int np = 0; np < 2; np++) {
                uint32_t boff = bRow + np * 4096 + bsw;
                uint32_t w0, w1, w2, w3;
                ldsm4(w0, w1, w2, w3, baseW + boff);
#pragma unroll
                for (int mt = 0; mt < 2; mt++) {
                    mma_f16(C[mt][2 * np],     ah[mt][0], ah[mt][1], ah[mt][2], ah[mt][3], w0, w1);
                    mma_f16(C[mt][2 * np + 1], ah[mt][0], ah[mt][1], ah[mt][2], ah[mt][3], w2, w3);
                }
            }
        }
        __syncthreads();

#pragma unroll
        for (int mt = 0; mt < 2; mt++) {
            int ra = 32 * wr + 16 * mt + tr;
            int rb = ra + 8;
#pragma unroll
            for (int nt = 0; nt < 4; nt++) {
                int c = 32 * wc + 8 * nt + 2 * tcq;
                float v0 = C[mt][nt][0] + s_B[c];
                float v1 = C[mt][nt][1] + s_B[c + 1];
                float v2 = C[mt][nt][2] + s_B[c];
                float v3 = C[mt][nt][3] + s_B[c + 1];
                uint32_t cp = (uint32_t)(16 * wc + 4 * nt + tcq);
                stg32[(uint32_t)ra * 64u + (cp ^ (((uint32_t)ra & 7u) << 2))] =
                    h2u(__floats2half2_rn(v0, v1));
                stg32[(uint32_t)rb * 64u + (cp ^ (((uint32_t)rb & 7u) << 2))] =
                    h2u(__floats2half2_rn(v2, v3));
            }
        }
        __syncthreads();

#pragma unroll 4
        for (int r = grp * 16; r < grp * 16 + 16; r++) {
            int node = nb + r;
            if (node < NODES) {
                uint32_t hv = stg32[(uint32_t)r * 64u +
                                    ((uint32_t)wcp ^ (((uint32_t)r & 7u) << 2))];
                *(uint32_t*)&g_y1[(size_t)node * CH + wcc] = hv;
                __half2 h;
                memcpy(&h, &hv, 4);
                float2 f = __half22float2(h);
                as0 += f.x; aq0 += f.x * f.x;
                as1 += f.y; aq1 += f.y * f.y;
            }
        }
        __syncthreads();
    }
    ((float4*)sm)[tid] = make_float4(as0, aq0, as1, aq1);
    __syncthreads();
    if (tid < 64) {
        float4 a = ((float4*)sm)[tid], b = ((float4*)sm)[tid + 64];
        float4 cc = ((float4*)sm)[tid + 128], d = ((float4*)sm)[tid + 192];
        int c = tid * 2;
        atomicAdd(&g_sum[1][c],     a.x + b.x + cc.x + d.x);
        atomicAdd(&g_sq[1][c],      a.y + b.y + cc.y + d.y);
        atomicAdd(&g_sum[1][c + 1], a.z + b.z + cc.z + d.z);
        atomicAdd(&g_sq[1][c + 1],  a.w + b.w + cc.w + d.w);
    }
    grid_sync(1);

    // =============== PHASE C: pool over own tiles ===============
    {
        float mu0 = g_sum[1][wcc] * (1.f / NODES);
        float va0 = g_sq[1][wcc] * (1.f / NODES) - mu0 * mu0;
        float sc0 = g1[wcc] * rsqrtf(va0 + 1e-5f);
        float sh0 = bb1[wcc] - mu0 * sc0;
        float mu1 = g_sum[1][wcc + 1] * (1.f / NODES);
        float va1 = g_sq[1][wcc + 1] * (1.f / NODES) - mu1 * mu1;
        float sc1 = g1[wcc + 1] * rsqrtf(va1 + 1e-5f);
        float sh1 = bb1[wcc + 1] - mu1 * sc1;

#pragma unroll 1
        for (int tile = blockIdx.x; tile < NBLK; tile += PGRID) {
            int nb = tile * TM;
            int gcur = -1;
            float p0 = 0.f, p1 = 0.f;
#pragma unroll 4
            for (int r = grp * 16; r < grp * 16 + 16; r++) {
                int node = nb + r;
                if (node >= NODES) break;
                int gg = node / NPG;
                if (gg != gcur) {
                    if (gcur >= 0) {
                        atomicAdd(&g_pool[gcur * CH + wcc], p0);
                        atomicAdd(&g_pool[gcur * CH + wcc + 1], p1);
                    }
                    gcur = gg; p0 = 0.f; p1 = 0.f;
                }
                uint32_t hv = *(const uint32_t*)&g_y1[(size_t)node * CH + wcc];
                __half2 h;
                memcpy(&h, &hv, 4);
                float2 f = __half22float2(h);
                p0 += elu_fast(f.x * sc0 + sh0);
                p1 += elu_fast(f.y * sc1 + sh1);
            }
            if (gcur >= 0) {
                atomicAdd(&g_pool[gcur * CH + wcc], p0);
                atomicAdd(&g_pool[gcur * CH + wcc + 1], p1);
            }
        }
    }
    grid_sync(2);

    // =============== PHASE D: FC (CTAs 0..99, one graph each) ===============
    if (blockIdx.x < GRAPHS) {
        int g = blockIdx.x;
        int o = tid >> 2;
        int part = tid & 3;
        const float4* pool4 = (const float4*)&g_pool[g * CH];
        const float4* w4 = (const float4*)&fcW[o * CH];
        float s = 0.f;
#pragma unroll
        for (int i = 0; i < 8; i++) {
            int idx = part + 4 * i;
            float4 p = pool4[idx];
            float4 w = w4[idx];
            s += p.x * w.x + p.y * w.y + p.z * w.z + p.w * w.w;
        }
#pragma unroll
        for (int m = 1; m < 4; m <<= 1) s += __shfl_xor_sync(0xffffffff, s, m);
        if (part == 0) out[g * OUTD + o] = s * (1.f / NPG) + fcb[o];
    }
}

extern "C" void kernel_launch(void* const* d_in, const int* in_sizes, int n_in,
                              void* d_out, int out_size) {
    const float* x   = (const float*)d_in[0];
    const float* peW = (const float*)d_in[3];
    const float* peB = (const float*)d_in[4];
    const float* W0  = (const float*)d_in[5];
    const float* b0  = (const float*)d_in[8];
    const float* g0  = (const float*)d_in[9];
    const float* bb0 = (const float*)d_in[10];
    const float* W1  = (const float*)d_in[11];
    const float* b1  = (const float*)d_in[14];
    const float* g1  = (const float*)d_in[15];
    const float* bb1 = (const float*)d_in[16];
    const float* fcW = (const float*)d_in[17];
    const float* fcb = (const float*)d_in[18];
    float* out = (float*)d_out;

    static bool once = false;
    if (!once) {
        cudaFuncSetAttribute(k_fused, cudaFuncAttributeMaxDynamicSharedMemorySize, DSMEM);
        once = true;
    }

    k_prep<<<64, 256>>>(peW, peB, W0, b0, W1);
    k_fused<<<PGRID, 256, DSMEM>>>(x, b1, g0, bb0, g1, bb1, fcW, fcb, out);
}